// round 12
// baseline (speedup 1.0000x reference)
#include <cuda_runtime.h>
#include <math.h>

#define D_MODEL 1024
#define SEQ     4096
#define NHEAD   16
#define DK      64

// Scratch (allocation-free: __device__ globals)
__device__ float g_Q[SEQ * D_MODEL];
__device__ float g_K[SEQ * D_MODEL];
__device__ float g_V[SEQ * D_MODEL];
__device__ float g_O[SEQ * D_MODEL];

// ---------------------------------------------------------------------------
// tf32 helpers. cvt.rna (round-to-nearest) is REQUIRED: raw-bit truncation in
// the mma gives a correlated -2^-11 bias per operand -> ~1e-3 systematic error.
// ---------------------------------------------------------------------------
__device__ __forceinline__ unsigned f2tf(float x) {
    unsigned y;
    asm("cvt.rna.tf32.f32 %0, %1;" : "=r"(y) : "f"(x));
    return y;
}

// D += A(16x8) * B(8x8), tf32 in, fp32 accum
__device__ __forceinline__ void mma8(float* d, const unsigned* a, const unsigned* b) {
    asm volatile(
        "mma.sync.aligned.m16n8k8.row.col.f32.tf32.tf32.f32 "
        "{%0,%1,%2,%3}, {%4,%5,%6,%7}, {%8,%9}, {%0,%1,%2,%3};\n"
        : "+f"(d[0]), "+f"(d[1]), "+f"(d[2]), "+f"(d[3])
        : "r"(a[0]), "r"(a[1]), "r"(a[2]), "r"(a[3]), "r"(b[0]), "r"(b[1]));
}

// Permutation within each 8-wide k-block so that the (c, c+4) fragment pair is
// adjacent in smem -> every fragment load is one LDS.64.
__device__ __forceinline__ int kperm(int k) {
    return (k & ~7) + ((k & 3) << 1) + ((k >> 2) & 1);
}

// ============================================================================
// GEMM core: C[M,1024] = A[M,1024] @ W[1024,1024]^T + bias  (tf32 mma, NT)
// Tile 128x128x16, 8 warps as 2(M)x4(N), warp tile 64x32.
// DOUBLE-BUFFERED smem: one __syncthreads per 16-k slab.
// ============================================================================
#define GSTR 24
#define GBUF (128 * GSTR)

__device__ __forceinline__ void gemm_store_slab(unsigned* ad, unsigned* bd,
                                                float4 av0, float4 av1,
                                                float4 wv0, float4 wv1) {
    const float aj[8] = {av0.x, av0.y, av0.z, av0.w, av1.x, av1.y, av1.z, av1.w};
    const float wj[8] = {wv0.x, wv0.y, wv0.z, wv0.w, wv1.x, wv1.y, wv1.z, wv1.w};
#pragma unroll
    for (int j = 0; j < 8; j++) {
        const int p = ((j & 3) << 1) + (j >> 2);
        ad[p] = f2tf(aj[j]);
        bd[p] = f2tf(wj[j]);
    }
}

__device__ __forceinline__ void gemm_core(const float* __restrict__ A,
                                          const float* __restrict__ W,
                                          const float* __restrict__ bias,
                                          float* __restrict__ C,
                                          int bx, int by) {
    extern __shared__ unsigned gsm[];
    unsigned* As = gsm;              // [2][128*GSTR]
    unsigned* Bs = gsm + 2 * GBUF;   // [2][128*GSTR]

    const int tid  = threadIdx.x;
    const int lane = tid & 31;
    const int warp = tid >> 5;
    const int g = lane >> 2, c = lane & 3;
    const int wm = (warp >> 2) * 64;
    const int wn = (warp & 3) * 32;
    const int bm = by * 128;
    const int bn = bx * 128;

    const int srow = tid >> 1;
    const int sk   = (tid & 1) * 8;
    const float* Ap = A + (bm + srow) * D_MODEL + sk;
    const float* Wp = W + (bn + srow) * D_MODEL + sk;
    unsigned* adst = As + srow * GSTR + sk;
    unsigned* bdst = Bs + srow * GSTR + sk;

    float acc[4][4][4];
#pragma unroll
    for (int i = 0; i < 4; i++)
#pragma unroll
        for (int j = 0; j < 4; j++)
#pragma unroll
            for (int r = 0; r < 4; r++) acc[i][j][r] = 0.0f;

    {
        float4 av0 = *(const float4*)Ap;
        float4 av1 = *(const float4*)(Ap + 4);
        float4 wv0 = *(const float4*)Wp;
        float4 wv1 = *(const float4*)(Wp + 4);
        gemm_store_slab(adst, bdst, av0, av1, wv0, wv1);
    }
    __syncthreads();

    for (int k0 = 0; k0 < D_MODEL; k0 += 16) {
        const int buf = (k0 >> 4) & 1;
        const unsigned* Acur = As + buf * GBUF;
        const unsigned* Bcur = Bs + buf * GBUF;
        const bool more = (k0 + 16) < D_MODEL;

        float4 av0, av1, wv0, wv1;
        if (more) {
            av0 = *(const float4*)(Ap + k0 + 16);
            av1 = *(const float4*)(Ap + k0 + 20);
            wv0 = *(const float4*)(Wp + k0 + 16);
            wv1 = *(const float4*)(Wp + k0 + 20);
        }

#pragma unroll
        for (int s = 0; s < 2; s++) {
            unsigned af[4][4], bf[4][2];
#pragma unroll
            for (int ma = 0; ma < 4; ma++) {
                const uint2 t0 = *(const uint2*)(Acur + (wm + ma * 16 + g)     * GSTR + s * 8 + c * 2);
                const uint2 t1 = *(const uint2*)(Acur + (wm + ma * 16 + g + 8) * GSTR + s * 8 + c * 2);
                af[ma][0] = t0.x; af[ma][1] = t1.x; af[ma][2] = t0.y; af[ma][3] = t1.y;
            }
#pragma unroll
            for (int na = 0; na < 4; na++) {
                const uint2 t = *(const uint2*)(Bcur + (wn + na * 8 + g) * GSTR + s * 8 + c * 2);
                bf[na][0] = t.x; bf[na][1] = t.y;
            }
#pragma unroll
            for (int ma = 0; ma < 4; ma++)
#pragma unroll
                for (int na = 0; na < 4; na++)
                    mma8(acc[ma][na], af[ma], bf[na]);
        }

        if (more)
            gemm_store_slab(adst + (buf ^ 1) * GBUF, bdst + (buf ^ 1) * GBUF,
                            av0, av1, wv0, wv1);
        __syncthreads();
    }

#pragma unroll
    for (int na = 0; na < 4; na++) {
        const int col = bn + wn + na * 8 + 2 * c;
        const float2 bb = *(const float2*)(bias + col);
#pragma unroll
        for (int ma = 0; ma < 4; ma++) {
            const int r0 = bm + wm + ma * 16 + g;
            float2 v0 = {acc[ma][na][0] + bb.x, acc[ma][na][1] + bb.y};
            float2 v1 = {acc[ma][na][2] + bb.x, acc[ma][na][3] + bb.y};
            *(float2*)(C + r0 * D_MODEL + col)       = v0;
            *(float2*)(C + (r0 + 8) * D_MODEL + col) = v1;
        }
    }
}

// Fused Q/K/V projection: blockIdx.z selects {query,key,value} x {Wq,Wk,Wv}.
__global__ __launch_bounds__(256, 2)
void gemm_qkv(const float* __restrict__ xq, const float* __restrict__ xk,
              const float* __restrict__ xv,
              const float* __restrict__ Wq, const float* __restrict__ bq,
              const float* __restrict__ Wk, const float* __restrict__ bk,
              const float* __restrict__ Wv, const float* __restrict__ bv,
              float* __restrict__ Cq, float* __restrict__ Ck, float* __restrict__ Cv) {
    const float *A, *W, *b;
    float* C;
    if (blockIdx.z == 0)      { A = xq; W = Wq; b = bq; C = Cq; }
    else if (blockIdx.z == 1) { A = xk; W = Wk; b = bk; C = Ck; }
    else                      { A = xv; W = Wv; b = bv; C = Cv; }
    gemm_core(A, W, b, C, blockIdx.x, blockIdx.y);
}

__global__ __launch_bounds__(256, 2)
void gemm_one(const float* __restrict__ A, const float* __restrict__ W,
              const float* __restrict__ bias, float* __restrict__ C) {
    gemm_core(A, W, bias, C, blockIdx.x, blockIdx.y);
}

// ============================================================================
// Flash attention, tf32 mma. One CTA = (head, 128-query block), 2 CTAs/SM.
// 8 warps, each owns 16 query rows -> softmax warp-local. 64-key blocks.
//  - K/V DOUBLE-BUFFERED in smem: LDG for block kb+1 at loop top (hidden under
//    QK), STS after QK, ONE __syncthreads per block.
//  - P never touches smem: S-accum -> PV A-fragment layout via quad shuffles.
// Qs/Ks in kperm layout (stride 72, conflict-free LDS.64 fragments);
// Vs plain (PV B-frags are scalar LDS with banks 8c+g covering 0..31).
// ============================================================================
#define ASTR  72
#define MQ    128
#define KVBUF (64 * ASTR)

__global__ __launch_bounds__(256, 2)
void attn_tf32(const float* __restrict__ Qb, const float* __restrict__ Kb,
               const float* __restrict__ Vb, float* __restrict__ Ob) {
    extern __shared__ unsigned smA[];
    unsigned* Qs = smA;                 // [MQ][ASTR]      perm(d)
    unsigned* Ks = Qs + MQ * ASTR;      // [2][64][ASTR]   perm(d)
    unsigned* Vs = Ks + 2 * KVBUF;      // [2][64][ASTR]   plain d

    const int tid = threadIdx.x, lane = tid & 31, warp = tid >> 5;
    const int g = lane >> 2, c = lane & 3;
    const int h = blockIdx.y, q0 = blockIdx.x * MQ, c0 = h * DK;
    const int wq = warp * 16;

    const float QS = 0.125f * 1.4426950408889634f;   // (1/sqrt(dk)) * log2(e)

    // ---- stage Q (scaled, tf32, perm) : 8 passes ----
#pragma unroll
    for (int p = 0; p < (MQ * DK) / (256 * 4); p++) {
        const int idx = p * 1024 + tid * 4;
        const int r = idx >> 6, d0 = idx & 63;
        const float4 v = *(const float4*)(Qb + (q0 + r) * D_MODEL + c0 + d0);
        unsigned* dst = Qs + r * ASTR;
        const float vv[4] = {v.x, v.y, v.z, v.w};
#pragma unroll
        for (int j = 0; j < 4; j++) dst[kperm(d0 + j)] = f2tf(vv[j] * QS);
    }

    // ---- stage K/V block 0 into buffer 0 ----
#pragma unroll
    for (int p = 0; p < 4; p++) {
        const int idx = p * 1024 + tid * 4;
        const int r = idx >> 6, d0 = idx & 63;
        const float4 kv = *(const float4*)(Kb + r * D_MODEL + c0 + d0);
        unsigned* kd = Ks + r * ASTR;
        kd[kperm(d0 + 0)] = f2tf(kv.x);
        kd[kperm(d0 + 1)] = f2tf(kv.y);
        kd[kperm(d0 + 2)] = f2tf(kv.z);
        kd[kperm(d0 + 3)] = f2tf(kv.w);
        const float4 vv = *(const float4*)(Vb + r * D_MODEL + c0 + d0);
        uint4 vt;
        vt.x = f2tf(vv.x); vt.y = f2tf(vv.y); vt.z = f2tf(vv.z); vt.w = f2tf(vv.w);
        *(uint4*)(Vs + r * ASTR + d0) = vt;
    }
    __syncthreads();

    float o[8][4];
    float mrun[2], lrun[2];
    mrun[0] = mrun[1] = -1e30f;
    lrun[0] = lrun[1] = 0.0f;
#pragma unroll
    for (int na = 0; na < 8; na++)
#pragma unroll
        for (int r = 0; r < 4; r++) o[na][r] = 0.0f;

    const int src0 = (lane & ~3) | (c >> 1);   // quad lane holding col c
    const int src2 = src0 + 2;                 // quad lane holding col c+4

    for (int kb = 0; kb < SEQ / 64; kb++) {
        const int cur = kb & 1, nxt = cur ^ 1;
        const unsigned* Kc = Ks + cur * KVBUF;
        const unsigned* Vc = Vs + cur * KVBUF;
        const bool more = (kb + 1) < (SEQ / 64);

        // ---- issue next block's global loads (latency hidden under QK) ----
        float4 kreg[4], vreg[4];
        if (more) {
            const int kr2 = (kb + 1) * 64;
#pragma unroll
            for (int p = 0; p < 4; p++) {
                const int idx = p * 1024 + tid * 4;
                const int r = idx >> 6, d0 = idx & 63;
                kreg[p] = *(const float4*)(Kb + (kr2 + r) * D_MODEL + c0 + d0);
                vreg[p] = *(const float4*)(Vb + (kr2 + r) * D_MODEL + c0 + d0);
            }
        }

        // ---- S = Q K^T (per warp: 16 q-rows x 64 keys) ----
        float sa[8][4];
#pragma unroll
        for (int na = 0; na < 8; na++)
#pragma unroll
            for (int r = 0; r < 4; r++) sa[na][r] = 0.0f;

#pragma unroll
        for (int s = 0; s < 8; s++) {
            unsigned aq[4];
            {
                const uint2 t0 = *(const uint2*)(Qs + (wq + g)     * ASTR + s * 8 + 2 * c);
                const uint2 t1 = *(const uint2*)(Qs + (wq + g + 8) * ASTR + s * 8 + 2 * c);
                aq[0] = t0.x; aq[1] = t1.x; aq[2] = t0.y; aq[3] = t1.y;
            }
#pragma unroll
            for (int na = 0; na < 8; na++) {
                const uint2 t = *(const uint2*)(Kc + (na * 8 + g) * ASTR + s * 8 + 2 * c);
                unsigned bk[2] = {t.x, t.y};
                mma8(sa[na], aq, bk);
            }
        }

        // ---- store staged K/V into the other buffer (frees staging regs) ----
        if (more) {
            unsigned* Kn = Ks + nxt * KVBUF;
            unsigned* Vn = Vs + nxt * KVBUF;
#pragma unroll
            for (int p = 0; p < 4; p++) {
                const int idx = p * 1024 + tid * 4;
                const int r = idx >> 6, d0 = idx & 63;
                unsigned* kd = Kn + r * ASTR;
                kd[kperm(d0 + 0)] = f2tf(kreg[p].x);
                kd[kperm(d0 + 1)] = f2tf(kreg[p].y);
                kd[kperm(d0 + 2)] = f2tf(kreg[p].z);
                kd[kperm(d0 + 3)] = f2tf(kreg[p].w);
                uint4 vt;
                vt.x = f2tf(vreg[p].x); vt.y = f2tf(vreg[p].y);
                vt.z = f2tf(vreg[p].z); vt.w = f2tf(vreg[p].w);
                *(uint4*)(Vn + r * ASTR + d0) = vt;
            }
        }

        // ---- online softmax + in-register S->A-fragment conversion ----
        float mx0 = -1e30f, mx1 = -1e30f;
#pragma unroll
        for (int na = 0; na < 8; na++) {
            mx0 = fmaxf(mx0, fmaxf(sa[na][0], sa[na][1]));
            mx1 = fmaxf(mx1, fmaxf(sa[na][2], sa[na][3]));
        }
        mx0 = fmaxf(mx0, __shfl_xor_sync(0xffffffffu, mx0, 1));
        mx0 = fmaxf(mx0, __shfl_xor_sync(0xffffffffu, mx0, 2));
        mx1 = fmaxf(mx1, __shfl_xor_sync(0xffffffffu, mx1, 1));
        mx1 = fmaxf(mx1, __shfl_xor_sync(0xffffffffu, mx1, 2));
        const float mn0 = fmaxf(mrun[0], mx0), mn1 = fmaxf(mrun[1], mx1);
        const float al0 = exp2f(mrun[0] - mn0), al1 = exp2f(mrun[1] - mn1);
        mrun[0] = mn0; mrun[1] = mn1;

        float rs0 = 0.0f, rs1 = 0.0f;
        unsigned ap[8][4];   // PV A-fragments, ap[key_block][frag]
#pragma unroll
        for (int na = 0; na < 8; na++) {
            const float p0 = exp2f(sa[na][0] - mn0);   // (row g,   col 2c)
            const float p1 = exp2f(sa[na][1] - mn0);   // (row g,   col 2c+1)
            const float p2 = exp2f(sa[na][2] - mn1);   // (row g+8, col 2c)
            const float p3 = exp2f(sa[na][3] - mn1);   // (row g+8, col 2c+1)
            rs0 += p0 + p1; rs1 += p2 + p3;
            const unsigned t0 = f2tf(p0), t1 = f2tf(p1);
            const unsigned t2 = f2tf(p2), t3 = f2tf(p3);
            unsigned e, od;
            e  = __shfl_sync(0xffffffffu, t0, src0);
            od = __shfl_sync(0xffffffffu, t1, src0);
            ap[na][0] = (c & 1) ? od : e;              // P(g,   c)
            e  = __shfl_sync(0xffffffffu, t2, src0);
            od = __shfl_sync(0xffffffffu, t3, src0);
            ap[na][1] = (c & 1) ? od : e;              // P(g+8, c)
            e  = __shfl_sync(0xffffffffu, t0, src2);
            od = __shfl_sync(0xffffffffu, t1, src2);
            ap[na][2] = (c & 1) ? od : e;              // P(g,   c+4)
            e  = __shfl_sync(0xffffffffu, t2, src2);
            od = __shfl_sync(0xffffffffu, t3, src2);
            ap[na][3] = (c & 1) ? od : e;              // P(g+8, c+4)
            o[na][0] *= al0; o[na][1] *= al0;
            o[na][2] *= al1; o[na][3] *= al1;
        }
        rs0 += __shfl_xor_sync(0xffffffffu, rs0, 1);
        rs0 += __shfl_xor_sync(0xffffffffu, rs0, 2);
        rs1 += __shfl_xor_sync(0xffffffffu, rs1, 1);
        rs1 += __shfl_xor_sync(0xffffffffu, rs1, 2);
        lrun[0] = lrun[0] * al0 + rs0;
        lrun[1] = lrun[1] * al1 + rs1;

        // ---- O += P V (contraction over 64 keys; ap[s] = keys s*8..s*8+7) ----
#pragma unroll
        for (int s = 0; s < 8; s++) {
#pragma unroll
            for (int na = 0; na < 8; na++) {
                unsigned bv[2];
                bv[0] = Vc[(s * 8 + c)     * ASTR + na * 8 + g];
                bv[1] = Vc[(s * 8 + c + 4) * ASTR + na * 8 + g];
                mma8(o[na], ap[s], bv);
            }
        }

        __syncthreads();   // nxt buffer full for all; cur free to overwrite
    }

    // ---- epilogue: O /= l, write concat-head layout [S, D_MODEL] ----
#pragma unroll
    for (int hf = 0; hf < 2; hf++) {
        const float inv = 1.0f / lrun[hf];
        const int row = q0 + wq + hf * 8 + g;
#pragma unroll
        for (int na = 0; na < 8; na++) {
            float2 w;
            w.x = o[na][2 * hf]     * inv;
            w.y = o[na][2 * hf + 1] * inv;
            *(float2*)(Ob + row * D_MODEL + c0 + na * 8 + 2 * c) = w;
        }
    }
}

// ============================================================================
// Launch
// ============================================================================
extern "C" void kernel_launch(void* const* d_in, const int* in_sizes, int n_in,
                              void* d_out, int out_size) {
    (void)in_sizes; (void)n_in; (void)out_size;
    const float* query = (const float*)d_in[0];
    const float* key   = (const float*)d_in[1];
    const float* value = (const float*)d_in[2];
    const float* Wq = (const float*)d_in[3];
    const float* bq = (const float*)d_in[4];
    const float* Wk = (const float*)d_in[5];
    const float* bk = (const float*)d_in[6];
    const float* Wv = (const float*)d_in[7];
    const float* bv = (const float*)d_in[8];
    const float* Wo = (const float*)d_in[9];
    const float* bo = (const float*)d_in[10];
    float* out = (float*)d_out;

    float *pQ, *pK, *pV, *pO;
    cudaGetSymbolAddress((void**)&pQ, g_Q);
    cudaGetSymbolAddress((void**)&pK, g_K);
    cudaGetSymbolAddress((void**)&pV, g_V);
    cudaGetSymbolAddress((void**)&pO, g_O);

    const int GSMEM = 4 * GBUF * (int)sizeof(unsigned);                    // 49152 B
    const int ASMEM = (MQ * ASTR + 4 * KVBUF) * (int)sizeof(unsigned);     // 110592 B
    cudaFuncSetAttribute(gemm_qkv, cudaFuncAttributeMaxDynamicSharedMemorySize, GSMEM);
    cudaFuncSetAttribute(gemm_one, cudaFuncAttributeMaxDynamicSharedMemorySize, GSMEM);
    cudaFuncSetAttribute(attn_tf32, cudaFuncAttributeMaxDynamicSharedMemorySize, ASMEM);

    dim3 gq(D_MODEL / 128, SEQ / 128, 3);   // (8, 32, 3)
    gemm_qkv<<<gq, 256, GSMEM>>>(query, key, value, Wq, bq, Wk, bk, Wv, bv,
                                 pQ, pK, pV);

    dim3 ga(SEQ / MQ, NHEAD);               // (32, 16)
    attn_tf32<<<ga, 256, ASMEM>>>(pQ, pK, pV, pO);

    dim3 gg(D_MODEL / 128, SEQ / 128);      // (8, 32)
    gemm_one<<<gg, 256, GSMEM>>>(pO, Wo, bo, out);
}